// round 11
// baseline (speedup 1.0000x reference)
#include <cuda_runtime.h>
#include <math.h>

#define MAXN 100000
#define MAXE 1600000
#define F 32
#define SCAN_B 1024
#define NBLK ((MAXN + SCAN_B - 1) / SCAN_B)

__device__ int      g_cnt [MAXN];       // in-degree (real edges)
__device__ int      g_row [MAXN + 1];   // CSR row offsets
__device__ int      g_cur [MAXN];       // fill cursors
__device__ int      g_csr [MAXE];       // CSR src indices
__device__ int      g_bsum[NBLK];
__device__ float    g_dinv[MAXN];
__device__ float    g_hA  [MAXN * F];   // gather source, pre-scaled by dinv[src]
__device__ float    g_hB  [MAXN * F];   // aggregate output (post-scaled by dinv[dst] downstream)
__device__ unsigned g_max [F];

// ---------------------------------------------------------------- init
__global__ void k_init(int n) {
    int i = blockIdx.x * blockDim.x + threadIdx.x;
    if (i < n) g_cnt[i] = 0;
    if (i < F) g_max[i] = 0u;
}

// ---------------------------------------------------------------- in-degree count (4 edges/thread)
__global__ void k_count(const int* __restrict__ ei, int E) {
    int e = (blockIdx.x * blockDim.x + threadIdx.x) * 4;
    if (e >= E) return;
    int4 d4 = *(const int4*)&ei[E + e];
    atomicAdd(&g_cnt[d4.x], 1);
    atomicAdd(&g_cnt[d4.y], 1);
    atomicAdd(&g_cnt[d4.z], 1);
    atomicAdd(&g_cnt[d4.w], 1);
}

// ---------------------------------------------------------------- scan pass 1: per-block exclusive scan
__global__ void k_scan1(int n) {
    __shared__ int sm[SCAN_B];
    int tid = threadIdx.x;
    int i = blockIdx.x * SCAN_B + tid;
    int v = (i < n) ? g_cnt[i] : 0;
    sm[tid] = v;
    __syncthreads();
#pragma unroll
    for (int off = 1; off < SCAN_B; off <<= 1) {
        int t = (tid >= off) ? sm[tid - off] : 0;
        __syncthreads();
        sm[tid] += t;
        __syncthreads();
    }
    if (i < n) g_row[i] = sm[tid] - v;            // exclusive
    if (tid == SCAN_B - 1) g_bsum[blockIdx.x] = sm[tid];
}

// ------------------------------- scan pass 2: warp-parallel exclusive scan of block sums (nb <= 128)
__global__ void k_scan2(int nb) {
    int lane = threadIdx.x;                       // 128 threads, 4 warps
    int wid  = lane >> 5;
    __shared__ int wsum[4];
    int v = (lane < nb) ? g_bsum[lane] : 0;
    int orig = v;
#pragma unroll
    for (int off = 1; off < 32; off <<= 1) {
        int t = __shfl_up_sync(0xffffffffu, v, off);
        if ((lane & 31) >= off) v += t;
    }
    if ((lane & 31) == 31) wsum[wid] = v;
    __syncthreads();
    int add = 0;
#pragma unroll
    for (int wv = 0; wv < 4; wv++) add += (wv < wid) ? wsum[wv] : 0;
    if (lane < nb) g_bsum[lane] = v + add - orig;  // exclusive
}

// -------- fused: row-offset fixup + cursor + dinv + layer1 dense hA = (x@W1)*dinv (thread-per-node)
__global__ void k_xw1(const float* __restrict__ x, const float* __restrict__ W1, int n, int E) {
    __shared__ float Ws[8 * F];
    int t = threadIdx.x;
    for (int i = t; i < 8 * F; i += blockDim.x) Ws[i] = W1[i];
    __syncthreads();
    int node = blockIdx.x * blockDim.x + t;
    if (node == 0) g_row[n] = E;
    if (node >= n) return;
    // CSR finalize for this node
    int r = g_row[node] + g_bsum[node / SCAN_B];
    g_row[node] = r;
    g_cur[node] = r;
    float d = rsqrtf((float)(g_cnt[node] + 1));
    g_dinv[node] = d;
    // dense
    float4 x0 = *(const float4*)&x[node * 8];
    float4 x1 = *(const float4*)&x[node * 8 + 4];
    float xv[8] = {x0.x, x0.y, x0.z, x0.w, x1.x, x1.y, x1.z, x1.w};
    float acc[F];
#pragma unroll
    for (int j = 0; j < F; j++) acc[j] = 0.f;
#pragma unroll
    for (int k = 0; k < 8; k++)
#pragma unroll
        for (int j = 0; j < F; j++)
            acc[j] = fmaf(xv[k], Ws[k * F + j], acc[j]);
    float4* pa = (float4*)&g_hA[node * F];
#pragma unroll
    for (int q = 0; q < 8; q++)
        pa[q] = make_float4(acc[q*4]*d, acc[q*4+1]*d, acc[q*4+2]*d, acc[q*4+3]*d);
}

// ---------------------------------------------------------------- CSR fill (4 edges/thread)
__global__ void k_fill(const int* __restrict__ ei, int E) {
    int e = (blockIdx.x * blockDim.x + threadIdx.x) * 4;
    if (e >= E) return;
    int4 s4 = *(const int4*)&ei[e];
    int4 d4 = *(const int4*)&ei[E + e];
    g_csr[atomicAdd(&g_cur[d4.x], 1)] = s4.x;
    g_csr[atomicAdd(&g_cur[d4.y], 1)] = s4.y;
    g_csr[atomicAdd(&g_cur[d4.z], 1)] = s4.z;
    g_csr[atomicAdd(&g_cur[d4.w], 1)] = s4.w;
}

// ---------------- aggregate (warp-per-node): hB[v] = hA[v] + sum_{s in N(v)} hA[s]
__global__ void k_agg(int n) {
    int lane = threadIdx.x & 31, w = threadIdx.x >> 5;
    int node = blockIdx.x * 8 + w;
    if (node >= n) return;
    int g  = lane >> 3;          // edge group 0..3
    int sl = lane & 7;           // float4 slot 0..7
    int start = g_row[node], end = g_row[node + 1];
    float4 acc0 = make_float4(0.f, 0.f, 0.f, 0.f);
    float4 acc1 = make_float4(0.f, 0.f, 0.f, 0.f);
    int base = start + g;
    // unrolled x2: two independent LDG.128 in flight per lane
    for (; base + 4 < end; base += 8) {
        int s0 = g_csr[base];
        int s1 = g_csr[base + 4];
        float4 v0 = *(const float4*)&g_hA[s0 * F + sl * 4];
        float4 v1 = *(const float4*)&g_hA[s1 * F + sl * 4];
        acc0.x += v0.x; acc0.y += v0.y; acc0.z += v0.z; acc0.w += v0.w;
        acc1.x += v1.x; acc1.y += v1.y; acc1.z += v1.z; acc1.w += v1.w;
    }
    if (base < end) {
        int s = g_csr[base];
        float4 v = *(const float4*)&g_hA[s * F + sl * 4];
        acc0.x += v.x; acc0.y += v.y; acc0.z += v.z; acc0.w += v.w;
    }
    acc0.x += acc1.x; acc0.y += acc1.y; acc0.z += acc1.z; acc0.w += acc1.w;
#pragma unroll
    for (int off = 16; off >= 8; off >>= 1) {
        acc0.x += __shfl_xor_sync(0xffffffffu, acc0.x, off);
        acc0.y += __shfl_xor_sync(0xffffffffu, acc0.y, off);
        acc0.z += __shfl_xor_sync(0xffffffffu, acc0.z, off);
        acc0.w += __shfl_xor_sync(0xffffffffu, acc0.w, off);
    }
    if (lane < 8) {
        float4 sv = *(const float4*)&g_hA[node * F + lane * 4];
        *(float4*)&g_hB[node * F + lane * 4] =
            make_float4(acc0.x + sv.x, acc0.y + sv.y, acc0.z + sv.z, acc0.w + sv.w);
    }
}

// -------- between layers (thread-per-node): r = relu(dinv*hB + b1); hA = (r@W2)*dinv
__global__ void k_mid(const float* __restrict__ b1, const float* __restrict__ W2, int n) {
    __shared__ float Ws[F * F];
    __shared__ float bs[F];
    int t = threadIdx.x;
    for (int i = t; i < F * F; i += blockDim.x) Ws[i] = W2[i];
    if (t < F) bs[t] = b1[t];
    __syncthreads();
    int node = blockIdx.x * blockDim.x + t;
    if (node >= n) return;
    float d = g_dinv[node];
    const float4* hb = (const float4*)&g_hB[node * F];
    float acc[F];
#pragma unroll
    for (int j = 0; j < F; j++) acc[j] = 0.f;
#pragma unroll
    for (int q = 0; q < 8; q++) {
        float4 hv = hb[q];
        float r0 = fmaxf(fmaf(d, hv.x, bs[q*4+0]), 0.f);
        float r1 = fmaxf(fmaf(d, hv.y, bs[q*4+1]), 0.f);
        float r2 = fmaxf(fmaf(d, hv.z, bs[q*4+2]), 0.f);
        float r3 = fmaxf(fmaf(d, hv.w, bs[q*4+3]), 0.f);
#pragma unroll
        for (int j = 0; j < F; j++) {
            acc[j] = fmaf(r0, Ws[(q*4+0) * F + j], acc[j]);
            acc[j] = fmaf(r1, Ws[(q*4+1) * F + j], acc[j]);
            acc[j] = fmaf(r2, Ws[(q*4+2) * F + j], acc[j]);
            acc[j] = fmaf(r3, Ws[(q*4+3) * F + j], acc[j]);
        }
    }
    float4* pa = (float4*)&g_hA[node * F];
#pragma unroll
    for (int q = 0; q < 8; q++)
        pa[q] = make_float4(acc[q*4]*d, acc[q*4+1]*d, acc[q*4+2]*d, acc[q*4+3]*d);
}

// ---------------------------------------------------------------- relu(dinv*hB+b2) then global max pool
__global__ void k_maxpool(const float* __restrict__ b2, int n) {
    __shared__ float sm[8][F];
    int lane = threadIdx.x & 31, w = threadIdx.x >> 5;
    float bias = b2[lane];
    float m = 0.f;
    for (int node = blockIdx.x * 8 + w; node < n; node += gridDim.x * 8) {
        float d = g_dinv[node];
        float v = fmaxf(fmaf(d, g_hB[node * F + lane], bias), 0.f);
        m = fmaxf(m, v);
    }
    sm[w][lane] = m;
    __syncthreads();
    if (w == 0) {
        float mm = sm[0][lane];
#pragma unroll
        for (int i = 1; i < 8; i++) mm = fmaxf(mm, sm[i][lane]);
        atomicMax(&g_max[lane], __float_as_uint(mm));
    }
}

// ---------------------------------------------------------------- FC head + log_softmax
__global__ void k_head(const float* __restrict__ fcW, const float* __restrict__ fcb,
                       float* __restrict__ out) {
    __shared__ float g[F];
    __shared__ float logits[5];
    int t = threadIdx.x;
    if (t < F) g[t] = __uint_as_float(g_max[t]);
    __syncthreads();
    if (t < 5) {
        float acc = fcb[t];
#pragma unroll
        for (int k = 0; k < F; k++) acc = fmaf(g[k], fcW[k * 5 + t], acc);
        logits[t] = acc;
    }
    __syncthreads();
    if (t == 0) {
        float m = logits[0];
#pragma unroll
        for (int c = 1; c < 5; c++) m = fmaxf(m, logits[c]);
        float s = 0.f;
#pragma unroll
        for (int c = 0; c < 5; c++) s += __expf(logits[c] - m);
        float lse = logf(s);
#pragma unroll
        for (int c = 0; c < 5; c++) out[c] = logits[c] - m - lse;
    }
}

// ================================================================ launch
extern "C" void kernel_launch(void* const* d_in, const int* in_sizes, int n_in,
                              void* d_out, int out_size) {
    const float* x   = (const float*)d_in[0];
    const int*   ei  = (const int*)d_in[1];
    const float* W1  = (const float*)d_in[2];
    const float* b1  = (const float*)d_in[3];
    const float* W2  = (const float*)d_in[4];
    const float* b2  = (const float*)d_in[5];
    const float* fcW = (const float*)d_in[6];
    const float* fcb = (const float*)d_in[7];
    float*       out = (float*)d_out;

    int n = in_sizes[0] / 8;       // 100000
    int E = in_sizes[1] / 2;       // 1600000

    const int TB = 256;
    int gridN   = (n + TB - 1) / TB;
    int gridE4  = (E / 4 + TB - 1) / TB;
    int gridNW  = (n + 7) / 8;                 // warp-per-node
    int nScanB  = (n + SCAN_B - 1) / SCAN_B;
    int gridD   = (n + 127) / 128;

    k_init   <<<gridN, TB>>>(n);
    k_count  <<<gridE4, TB>>>(ei, E);
    k_scan1  <<<nScanB, SCAN_B>>>(n);
    k_scan2  <<<1, 128>>>(nScanB);
    k_xw1    <<<gridD, 128>>>(x, W1, n, E);    // fused scan3 + dense
    k_fill   <<<gridE4, TB>>>(ei, E);
    k_agg    <<<gridNW, TB>>>(n);
    k_mid    <<<gridD, 128>>>(b1, W2, n);
    k_agg    <<<gridNW, TB>>>(n);
    k_maxpool<<<512, TB>>>(b2, n);
    k_head   <<<1, 32>>>(fcW, fcb, out);
}

// round 14
// speedup vs baseline: 1.1444x; 1.1444x over previous
#include <cuda_runtime.h>
#include <math.h>

#define MAXN 100000
#define MAXE 1600000
#define F 32
#define SCAN_B 1024
#define NBLK ((MAXN + SCAN_B - 1) / SCAN_B)   // 98

__device__ int      g_cnt [MAXN];       // in-degree; zeroed at load, re-zeroed by k_xw1 each run
__device__ int      g_row [MAXN + 1];   // CSR row offsets
__device__ int      g_cur [MAXN];       // fill cursors
__device__ int      g_csr [MAXE];       // CSR src indices
__device__ int      g_bsum[NBLK];       // scan1 block sums (unscanned)
__device__ float    g_dinv[MAXN];
__device__ float    g_hA  [MAXN * F];   // gather source, pre-scaled by dinv[src]
__device__ float    g_hB  [MAXN * F];   // aggregate output (post-scaled by dinv[dst] downstream)
__device__ unsigned g_max [F];          // zeroed at load, re-zeroed by head each run
__device__ unsigned g_done;             // last-block ticket, re-zeroed by head each run

// ---------------------------------------------------------------- in-degree count (4 edges/thread)
__global__ void k_count(const int* __restrict__ ei, int E) {
    int e = (blockIdx.x * blockDim.x + threadIdx.x) * 4;
    if (e >= E) return;
    int4 d4 = *(const int4*)&ei[E + e];
    atomicAdd(&g_cnt[d4.x], 1);
    atomicAdd(&g_cnt[d4.y], 1);
    atomicAdd(&g_cnt[d4.z], 1);
    atomicAdd(&g_cnt[d4.w], 1);
}

// ---------------------------------------------------------------- scan pass 1: per-block exclusive scan
__global__ void k_scan1(int n) {
    __shared__ int sm[SCAN_B];
    int tid = threadIdx.x;
    int i = blockIdx.x * SCAN_B + tid;
    int v = (i < n) ? g_cnt[i] : 0;
    sm[tid] = v;
    __syncthreads();
#pragma unroll
    for (int off = 1; off < SCAN_B; off <<= 1) {
        int t = (tid >= off) ? sm[tid - off] : 0;
        __syncthreads();
        sm[tid] += t;
        __syncthreads();
    }
    if (i < n) g_row[i] = sm[tid] - v;            // block-local exclusive
    if (tid == SCAN_B - 1) g_bsum[blockIdx.x] = sm[tid];
}

// ------ fused: redundant bsum scan + row/cursor/dinv fixup + cnt reset + layer1 dense (TB=128)
__global__ void k_xw1(const float* __restrict__ x, const float* __restrict__ W1,
                      int n, int E, int nb) {
    __shared__ float Ws[8 * F];
    __shared__ int   excl[128];
    int t = threadIdx.x;
    for (int i = t; i < 8 * F; i += blockDim.x) Ws[i] = W1[i];
    // per-block redundant exclusive scan of the (<=128) block sums
    int bv = (t < nb) ? g_bsum[t] : 0;
    excl[t] = bv;
    __syncthreads();
#pragma unroll
    for (int off = 1; off < 128; off <<= 1) {
        int tv = (t >= off) ? excl[t - off] : 0;
        __syncthreads();
        excl[t] += tv;
        __syncthreads();
    }
    int incl = excl[t];
    __syncthreads();
    excl[t] = incl - bv;                           // exclusive
    __syncthreads();

    int node = blockIdx.x * blockDim.x + t;
    if (node == 0) g_row[n] = E;
    if (node >= n) return;
    // CSR finalize for this node
    int r = g_row[node] + excl[node / SCAN_B];
    g_row[node] = r;
    g_cur[node] = r;
    int cnt = g_cnt[node];
    g_cnt[node] = 0;                               // restore invariant for next replay
    float d = rsqrtf((float)(cnt + 1));
    g_dinv[node] = d;
    // dense: hA = (x@W1)*dinv
    float4 x0 = *(const float4*)&x[node * 8];
    float4 x1 = *(const float4*)&x[node * 8 + 4];
    float xv[8] = {x0.x, x0.y, x0.z, x0.w, x1.x, x1.y, x1.z, x1.w};
    float acc[F];
#pragma unroll
    for (int j = 0; j < F; j++) acc[j] = 0.f;
#pragma unroll
    for (int k = 0; k < 8; k++)
#pragma unroll
        for (int j = 0; j < F; j++)
            acc[j] = fmaf(xv[k], Ws[k * F + j], acc[j]);
    float4* pa = (float4*)&g_hA[node * F];
#pragma unroll
    for (int q = 0; q < 8; q++)
        pa[q] = make_float4(acc[q*4]*d, acc[q*4+1]*d, acc[q*4+2]*d, acc[q*4+3]*d);
}

// ---------------------------------------------------------------- CSR fill (4 edges/thread)
__global__ void k_fill(const int* __restrict__ ei, int E) {
    int e = (blockIdx.x * blockDim.x + threadIdx.x) * 4;
    if (e >= E) return;
    int4 s4 = *(const int4*)&ei[e];
    int4 d4 = *(const int4*)&ei[E + e];
    g_csr[atomicAdd(&g_cur[d4.x], 1)] = s4.x;
    g_csr[atomicAdd(&g_cur[d4.y], 1)] = s4.y;
    g_csr[atomicAdd(&g_cur[d4.z], 1)] = s4.z;
    g_csr[atomicAdd(&g_cur[d4.w], 1)] = s4.w;
}

// ---------------- aggregate (warp-per-node): hB[v] = hA[v] + sum_{s in N(v)} hA[s]  (R7 form)
__global__ void k_agg(int n) {
    int lane = threadIdx.x & 31, w = threadIdx.x >> 5;
    int node = blockIdx.x * 8 + w;
    if (node >= n) return;
    int g  = lane >> 3;          // edge group 0..3
    int sl = lane & 7;           // float4 slot 0..7
    int start = g_row[node], end = g_row[node + 1];
    float4 acc = make_float4(0.f, 0.f, 0.f, 0.f);
    for (int base = start + g; base < end; base += 4) {
        int s = g_csr[base];
        float4 v = *(const float4*)&g_hA[s * F + sl * 4];
        acc.x += v.x; acc.y += v.y; acc.z += v.z; acc.w += v.w;
    }
#pragma unroll
    for (int off = 16; off >= 8; off >>= 1) {
        acc.x += __shfl_xor_sync(0xffffffffu, acc.x, off);
        acc.y += __shfl_xor_sync(0xffffffffu, acc.y, off);
        acc.z += __shfl_xor_sync(0xffffffffu, acc.z, off);
        acc.w += __shfl_xor_sync(0xffffffffu, acc.w, off);
    }
    if (lane < 8) {
        float4 sv = *(const float4*)&g_hA[node * F + lane * 4];
        *(float4*)&g_hB[node * F + lane * 4] =
            make_float4(acc.x + sv.x, acc.y + sv.y, acc.z + sv.z, acc.w + sv.w);
    }
}

// -------- between layers (thread-per-node): r = relu(dinv*hB + b1); hA = (r@W2)*dinv
__global__ void k_mid(const float* __restrict__ b1, const float* __restrict__ W2, int n) {
    __shared__ float Ws[F * F];
    __shared__ float bs[F];
    int t = threadIdx.x;
    for (int i = t; i < F * F; i += blockDim.x) Ws[i] = W2[i];
    if (t < F) bs[t] = b1[t];
    __syncthreads();
    int node = blockIdx.x * blockDim.x + t;
    if (node >= n) return;
    float d = g_dinv[node];
    const float4* hb = (const float4*)&g_hB[node * F];
    float acc[F];
#pragma unroll
    for (int j = 0; j < F; j++) acc[j] = 0.f;
#pragma unroll
    for (int q = 0; q < 8; q++) {
        float4 hv = hb[q];
        float r0 = fmaxf(fmaf(d, hv.x, bs[q*4+0]), 0.f);
        float r1 = fmaxf(fmaf(d, hv.y, bs[q*4+1]), 0.f);
        float r2 = fmaxf(fmaf(d, hv.z, bs[q*4+2]), 0.f);
        float r3 = fmaxf(fmaf(d, hv.w, bs[q*4+3]), 0.f);
#pragma unroll
        for (int j = 0; j < F; j++) {
            acc[j] = fmaf(r0, Ws[(q*4+0) * F + j], acc[j]);
            acc[j] = fmaf(r1, Ws[(q*4+1) * F + j], acc[j]);
            acc[j] = fmaf(r2, Ws[(q*4+2) * F + j], acc[j]);
            acc[j] = fmaf(r3, Ws[(q*4+3) * F + j], acc[j]);
        }
    }
    float4* pa = (float4*)&g_hA[node * F];
#pragma unroll
    for (int q = 0; q < 8; q++)
        pa[q] = make_float4(acc[q*4]*d, acc[q*4+1]*d, acc[q*4+2]*d, acc[q*4+3]*d);
}

// ---------------- fused maxpool + FC head + log_softmax (last-block pattern)
__global__ void k_pool_head(const float* __restrict__ b2, const float* __restrict__ fcW,
                            const float* __restrict__ fcb, float* __restrict__ out, int n) {
    __shared__ float sm[8][F];
    __shared__ bool  last;
    int lane = threadIdx.x & 31, w = threadIdx.x >> 5;
    float bias = b2[lane];
    float m = 0.f;
    for (int node = blockIdx.x * 8 + w; node < n; node += gridDim.x * 8) {
        float d = g_dinv[node];
        m = fmaxf(m, fmaxf(fmaf(d, g_hB[node * F + lane], bias), 0.f));
    }
    sm[w][lane] = m;
    __syncthreads();
    if (w == 0) {
        float mm = sm[0][lane];
#pragma unroll
        for (int i = 1; i < 8; i++) mm = fmaxf(mm, sm[i][lane]);
        atomicMax(&g_max[lane], __float_as_uint(mm));
        __threadfence();                      // publish before ticket
    }
    __syncthreads();
    if (threadIdx.x == 0)
        last = (atomicAdd(&g_done, 1u) == gridDim.x - 1);
    __syncthreads();
    if (!last) return;
    // last block: head on warp 0
    if (w == 0) {
        float gv = __uint_as_float(*(volatile unsigned*)&g_max[lane]);
        sm[0][lane] = gv;
        __syncwarp();
        float logit = 0.f;
        if (lane < 5) {
            logit = fcb[lane];
#pragma unroll
            for (int k = 0; k < F; k++) logit = fmaf(sm[0][k], fcW[k * 5 + lane], logit);
        }
        // log_softmax across 5 lanes via shuffles (all lanes participate)
        float lv = (lane < 5) ? logit : -1e30f;
        float mx = lv;
#pragma unroll
        for (int off = 4; off > 0; off >>= 1) mx = fmaxf(mx, __shfl_xor_sync(0xffffffffu, mx, off));
        // lanes 0..7 cover lanes 0..4 data after 3 steps; do full 5-step to be safe over 32 lanes
#pragma unroll
        for (int off = 8; off < 32; off <<= 1) mx = fmaxf(mx, __shfl_xor_sync(0xffffffffu, mx, off));
        float ex = (lane < 5) ? __expf(logit - mx) : 0.f;
        float s = ex;
#pragma unroll
        for (int off = 1; off < 32; off <<= 1) s += __shfl_xor_sync(0xffffffffu, s, off);
        float lse = logf(s);
        if (lane < 5) out[lane] = logit - mx - lse;
        // restore invariants for next replay
        g_max[lane] = 0u;
        if (lane == 0) g_done = 0u;
    }
}

// ================================================================ launch
extern "C" void kernel_launch(void* const* d_in, const int* in_sizes, int n_in,
                              void* d_out, int out_size) {
    const float* x   = (const float*)d_in[0];
    const int*   ei  = (const int*)d_in[1];
    const float* W1  = (const float*)d_in[2];
    const float* b1  = (const float*)d_in[3];
    const float* W2  = (const float*)d_in[4];
    const float* b2  = (const float*)d_in[5];
    const float* fcW = (const float*)d_in[6];
    const float* fcb = (const float*)d_in[7];
    float*       out = (float*)d_out;

    int n = in_sizes[0] / 8;       // 100000
    int E = in_sizes[1] / 2;       // 1600000

    const int TB = 256;
    int gridE4  = (E / 4 + TB - 1) / TB;
    int gridNW  = (n + 7) / 8;                 // warp-per-node
    int nScanB  = (n + SCAN_B - 1) / SCAN_B;   // 98
    int gridD   = (n + 127) / 128;

    k_count    <<<gridE4, TB>>>(ei, E);
    k_scan1    <<<nScanB, SCAN_B>>>(n);
    k_xw1      <<<gridD, 128>>>(x, W1, n, E, nScanB);   // fused scan2+scan3+dense+reset
    k_fill     <<<gridE4, TB>>>(ei, E);
    k_agg      <<<gridNW, TB>>>(n);
    k_mid      <<<gridD, 128>>>(b1, W2, n);
    k_agg      <<<gridNW, TB>>>(n);
    k_pool_head<<<512, TB>>>(b2, fcW, fcb, out, n);
}